// round 2
// baseline (speedup 1.0000x reference)
#include <cuda_runtime.h>
#include <cuda_bf16.h>
#include <cstdint>

// Problem constants (QRNNLayer: B=16, S=2048, D=1024, H=1024)
#define BB 16
#define SS 2048
#define DD 1024
#define HH 1024
#define MM (BB * SS)        // 32768 rows
#define NN (3 * HH)         // 3072 cols
#define KK DD               // 1024

// Chunked scan config
#define NCH 32
#define CHLEN 64            // NCH * CHLEN == SS

// Scratch (allocation-free: __device__ globals)
__device__ float g_y[(size_t)MM * NN];          // activated gates [M, 3H]
__device__ float g_Ac[BB * HH * NCH];           // per-chunk alpha product
__device__ float g_Bc[BB * HH * NCH];           // per-chunk local scan end
__device__ float g_C0[BB * HH * NCH];           // per-chunk initial carry

// ---------------------------------------------------------------------------
// Kernel 1: tiled SGEMM  Y[m,n] = sum_k inp[m,k]*W[n,k] + b[n], fused activation
// BM=BN=128, BK=8, 256 threads, 8x8 microtile, register-prefetch double buffer
// ---------------------------------------------------------------------------
__global__ void __launch_bounds__(256, 2) gemm_act_kernel(
    const float* __restrict__ A,     // [M, K]
    const float* __restrict__ W,     // [N, K]
    const float* __restrict__ bias)  // [N]
{
    __shared__ float As[8][132];     // pad 132: conflict-free stores & 16B-aligned rows
    __shared__ float Bs[8][132];

    const int tid = threadIdx.x;
    const int m0 = blockIdx.y * 128;
    const int n0 = blockIdx.x * 128;

    const int lrow = tid >> 1;          // 0..127
    const int lcol = (tid & 1) << 2;    // 0 or 4

    const float* aptr = A + (size_t)(m0 + lrow) * KK + lcol;
    const float* bptr = W + (size_t)(n0 + lrow) * KK + lcol;

    const int tr = (tid >> 4) << 3;     // 0..120 step 8
    const int tc = (tid & 15) << 3;     // 0..120 step 8

    float acc[8][8];
#pragma unroll
    for (int i = 0; i < 8; i++)
#pragma unroll
        for (int j = 0; j < 8; j++) acc[i][j] = 0.0f;

    float4 av = *(const float4*)(aptr);
    float4 bv = *(const float4*)(bptr);

    for (int k0 = 0; k0 < KK; k0 += 8) {
        As[lcol + 0][lrow] = av.x;
        As[lcol + 1][lrow] = av.y;
        As[lcol + 2][lrow] = av.z;
        As[lcol + 3][lrow] = av.w;
        Bs[lcol + 0][lrow] = bv.x;
        Bs[lcol + 1][lrow] = bv.y;
        Bs[lcol + 2][lrow] = bv.z;
        Bs[lcol + 3][lrow] = bv.w;
        __syncthreads();

        if (k0 + 8 < KK) {   // prefetch next tile while computing this one
            av = *(const float4*)(aptr + k0 + 8);
            bv = *(const float4*)(bptr + k0 + 8);
        }

#pragma unroll
        for (int k = 0; k < 8; k++) {
            float4 a0 = *(const float4*)&As[k][tr];
            float4 a1 = *(const float4*)&As[k][tr + 4];
            float4 b0 = *(const float4*)&Bs[k][tc];
            float4 b1 = *(const float4*)&Bs[k][tc + 4];
            float ra[8] = {a0.x, a0.y, a0.z, a0.w, a1.x, a1.y, a1.z, a1.w};
            float rb[8] = {b0.x, b0.y, b0.z, b0.w, b1.x, b1.y, b1.z, b1.w};
#pragma unroll
            for (int i = 0; i < 8; i++)
#pragma unroll
                for (int j = 0; j < 8; j++)
                    acc[i][j] = fmaf(ra[i], rb[j], acc[i][j]);
        }
        __syncthreads();
    }

    // Epilogue: bias + activation (segment 0: tanh, segments 1,2: sigmoid)
    const int seg = n0 >> 10;   // BN=128 divides 1024, so whole block is one segment
    float bb[8];
#pragma unroll
    for (int j = 0; j < 8; j++) bb[j] = bias[n0 + tc + j];

#pragma unroll
    for (int i = 0; i < 8; i++) {
        float* yrow = g_y + (size_t)(m0 + tr + i) * NN + n0 + tc;
#pragma unroll
        for (int j = 0; j < 8; j++) {
            float v = acc[i][j] + bb[j];
            if (seg == 0) {
                v = tanhf(v);
            } else {
                v = 1.0f / (1.0f + __expf(-v));
            }
            yrow[j] = v;
        }
    }
}

// ---------------------------------------------------------------------------
// Scan pass 1: per (b, chunk, h) compute chunk composition
//   step map: c -> (1-f)*c + f*z.  A = prod(1-f), B = scan result with c0=0.
// idx = ((b*NCH + ch)*H + h), consecutive threads -> consecutive h (coalesced)
// ---------------------------------------------------------------------------
__global__ void __launch_bounds__(256) scan_pass1() {
    const int idx = blockIdx.x * 256 + threadIdx.x;
    const int h = idx & (HH - 1);
    const int rest = idx >> 10;          // b*NCH + ch
    const int ch = rest & (NCH - 1);
    const int b = rest >> 5;

    const float* base = g_y + (size_t)(b * SS + ch * CHLEN) * NN + h;

    float c = 0.0f, a = 1.0f;
#pragma unroll 8
    for (int t = 0; t < CHLEN; t++) {
        float z = base[(size_t)t * NN];
        float f = base[(size_t)t * NN + HH];
        c = fmaf(f, z - c, c);
        a *= (1.0f - f);
    }
    const int o = (ch * BB + b) * HH + h;   // [NCH][B][H] layout
    g_Ac[o] = a;
    g_Bc[o] = c;
}

// ---------------------------------------------------------------------------
// Scan pass 2: per (b, h), sequential 32-step carry scan across chunks
// ---------------------------------------------------------------------------
__global__ void __launch_bounds__(256) scan_pass2() {
    const int idx = blockIdx.x * 256 + threadIdx.x;   // b*H + h
    const int h = idx & (HH - 1);
    const int b = idx >> 10;

    float carry = 0.0f;
#pragma unroll
    for (int ch = 0; ch < NCH; ch++) {
        const int o = (ch * BB + b) * HH + h;
        g_C0[o] = carry;
        carry = fmaf(g_Ac[o], carry, g_Bc[o]);
    }
}

// ---------------------------------------------------------------------------
// Scan pass 3: re-run chunk scan with correct carry, write output + c_last
// ---------------------------------------------------------------------------
__global__ void __launch_bounds__(256) scan_pass3(float* __restrict__ out) {
    const int idx = blockIdx.x * 256 + threadIdx.x;
    const int h = idx & (HH - 1);
    const int rest = idx >> 10;
    const int ch = rest & (NCH - 1);
    const int b = rest >> 5;

    const float* base = g_y + (size_t)(b * SS + ch * CHLEN) * NN + h;
    float* orow = out + (size_t)(b * SS + ch * CHLEN) * HH + h;

    float c = g_C0[(ch * BB + b) * HH + h];
#pragma unroll 8
    for (int t = 0; t < CHLEN; t++) {
        float z = base[(size_t)t * NN];
        float f = base[(size_t)t * NN + HH];
        float o = base[(size_t)t * NN + 2 * HH];
        c = fmaf(f, z - c, c);
        orow[(size_t)t * HH] = o * c;
    }
    if (ch == NCH - 1) {
        // c_last output appended after the main [B,S,H] output
        out[(size_t)BB * SS * HH + b * HH + h] = c;
    }
}

// ---------------------------------------------------------------------------
extern "C" void kernel_launch(void* const* d_in, const int* in_sizes, int n_in,
                              void* d_out, int out_size) {
    const float* inp  = (const float*)d_in[0];   // [B, S, D]
    const float* W    = (const float*)d_in[1];   // [3H, D]
    const float* bias = (const float*)d_in[2];   // [3H]
    float* out = (float*)d_out;                  // [B,S,H] then [B,H]

    dim3 ggrid(NN / 128, MM / 128);              // (24, 256)
    gemm_act_kernel<<<ggrid, 256>>>(inp, W, bias);

    scan_pass1<<<(BB * HH * NCH) / 256, 256>>>();
    scan_pass2<<<(BB * HH) / 256, 256>>>();
    scan_pass3<<<(BB * HH * NCH) / 256, 256>>>(out);
}

// round 5
// speedup vs baseline: 2.6937x; 2.6937x over previous
#include <cuda_runtime.h>
#include <cuda_bf16.h>
#include <cstdint>

// Problem constants (QRNNLayer: B=16, S=2048, D=1024, H=1024)
#define BB 16
#define SS 2048
#define DD 1024
#define HH 1024
#define MM (BB * SS)        // 32768 rows
#define NN (3 * HH)         // 3072 cols
#define KK DD               // 1024
#define KEXT (3 * KK)       // 3072 extended K for bf16x3 split

// Chunked scan config
#define NCH 32
#define CHLEN 64

// Scratch (allocation-free: __device__ globals)
__device__ float g_y[(size_t)MM * NN];                 // activated gates [M, 3H]
__device__ __nv_bfloat16 g_Ahi[(size_t)MM * KK];
__device__ __nv_bfloat16 g_Alo[(size_t)MM * KK];
__device__ __nv_bfloat16 g_Bhi[(size_t)NN * KK];
__device__ __nv_bfloat16 g_Blo[(size_t)NN * KK];
__device__ float g_Ac[BB * HH * NCH];
__device__ float g_Bc[BB * HH * NCH];
__device__ float g_C0[BB * HH * NCH];

// ---------------------------------------------------------------------------
// bf16 hi/lo split conversion (vectorized float4 -> 4x bf16 hi + 4x bf16 lo)
// ---------------------------------------------------------------------------
__global__ void __launch_bounds__(256) split_kernel(
    const float* __restrict__ src, __nv_bfloat16* __restrict__ hi,
    __nv_bfloat16* __restrict__ lo, int n4)
{
    int i = blockIdx.x * 256 + threadIdx.x;
    if (i >= n4) return;
    float4 v = ((const float4*)src)[i];
    __nv_bfloat16 h0 = __float2bfloat16(v.x);
    __nv_bfloat16 h1 = __float2bfloat16(v.y);
    __nv_bfloat16 h2 = __float2bfloat16(v.z);
    __nv_bfloat16 h3 = __float2bfloat16(v.w);
    __nv_bfloat16 l0 = __float2bfloat16(v.x - __bfloat162float(h0));
    __nv_bfloat16 l1 = __float2bfloat16(v.y - __bfloat162float(h1));
    __nv_bfloat16 l2 = __float2bfloat16(v.z - __bfloat162float(h2));
    __nv_bfloat16 l3 = __float2bfloat16(v.w - __bfloat162float(h3));
    ushort4 ph, pl;
    ph.x = __bfloat16_as_ushort(h0); ph.y = __bfloat16_as_ushort(h1);
    ph.z = __bfloat16_as_ushort(h2); ph.w = __bfloat16_as_ushort(h3);
    pl.x = __bfloat16_as_ushort(l0); pl.y = __bfloat16_as_ushort(l1);
    pl.z = __bfloat16_as_ushort(l2); pl.w = __bfloat16_as_ushort(l3);
    ((ushort4*)hi)[i] = ph;
    ((ushort4*)lo)[i] = pl;
}

// ---------------------------------------------------------------------------
// Tensor-core GEMM: Y = act( A_ext @ B_ext^T + bias ), K_ext = 3072 bf16
//   seg0: Ahi*Bhi, seg1: Alo*Bhi, seg2: Ahi*Blo   (bf16x3 ~ fp32 precision)
// Block tile 128x128, BK=32, 8 warps (2m x 4n), warp tile 64x32, m16n8k16.
// cp.async double-buffered smem, XOR swizzle (16B chunks), ldmatrix frags.
// ---------------------------------------------------------------------------
__device__ __forceinline__ void cp16(uint32_t saddr, const void* g) {
    asm volatile("cp.async.cg.shared.global [%0], [%1], 16;\n" :: "r"(saddr), "l"(g));
}
__device__ __forceinline__ uint32_t smem_u32(const void* p) {
    return (uint32_t)__cvta_generic_to_shared(p);
}

#define STAGE_BYTES 8192   // 128 rows * 64 B (32 bf16)

__global__ void __launch_bounds__(256) gemm_bf16x3(const float* __restrict__ bias)
{
    __shared__ __align__(128) __nv_bfloat16 sA[2][128 * 32];
    __shared__ __align__(128) __nv_bfloat16 sB[2][128 * 32];

    const int tid  = threadIdx.x;
    const int m0   = blockIdx.y * 128;
    const int n0   = blockIdx.x * 128;
    const int warp = tid >> 5;
    const int lane = tid & 31;
    const int wm   = warp >> 2;   // 0..1 -> m offset 64*wm
    const int wn   = warp & 3;    // 0..3 -> n offset 32*wn

    const uint32_t sAb = smem_u32(&sA[0][0]);
    const uint32_t sBb = smem_u32(&sB[0][0]);

    // loader mapping: chunk id c = tid + i*256; row = c>>2, chunk = c&3 (16B)
    const int lrow0 = tid >> 2;
    const int lch   = tid & 3;

    float acc[4][4][4];
#pragma unroll
    for (int i = 0; i < 4; i++)
#pragma unroll
        for (int j = 0; j < 4; j++)
#pragma unroll
            for (int r = 0; r < 4; r++) acc[i][j][r] = 0.0f;

    // --- stage loader ---
    auto load_stage = [&](int stage, int it) {
        const int seg = it >> 5;             // 0,1,2 (32 iters each)
        const int kk  = (it & 31) * 32;
        const __nv_bfloat16* Ag = (seg == 1) ? g_Alo : g_Ahi;
        const __nv_bfloat16* Bg = (seg == 2) ? g_Blo : g_Bhi;
#pragma unroll
        for (int i = 0; i < 2; i++) {
            const int row = lrow0 + i * 64;
            const int sw  = lch ^ ((row >> 1) & 3);
            const uint32_t so = (uint32_t)(stage * STAGE_BYTES + row * 64 + sw * 16);
            cp16(sAb + so, Ag + (size_t)(m0 + row) * KK + kk + lch * 8);
            cp16(sBb + so, Bg + (size_t)(n0 + row) * KK + kk + lch * 8);
        }
        asm volatile("cp.async.commit_group;\n" ::);
    };

    load_stage(0, 0);

    const int NIT = KEXT / 32;   // 96
    for (int it = 0; it < NIT; ++it) {
        if (it + 1 < NIT) {
            load_stage((it + 1) & 1, it + 1);
            asm volatile("cp.async.wait_group 1;\n" ::);
        } else {
            asm volatile("cp.async.wait_group 0;\n" ::);
        }
        __syncthreads();

        const int stage = it & 1;
        const uint32_t aBase = sAb + stage * STAGE_BYTES;
        const uint32_t bBase = sBb + stage * STAGE_BYTES;

#pragma unroll
        for (int ks = 0; ks < 2; ks++) {
            uint32_t aF[4][4];
            uint32_t bF[4][2];
            // A fragments: 4 m-tiles of 16 rows, ldmatrix.x4 each
#pragma unroll
            for (int mt = 0; mt < 4; mt++) {
                const int r  = wm * 64 + mt * 16 + (lane & 15);
                const int ch = ks * 2 + (lane >> 4);
                const int sw = ch ^ ((r >> 1) & 3);
                const uint32_t addr = aBase + r * 64 + sw * 16;
                asm volatile(
                    "ldmatrix.sync.aligned.m8n8.x4.shared.b16 {%0,%1,%2,%3}, [%4];\n"
                    : "=r"(aF[mt][0]), "=r"(aF[mt][1]), "=r"(aF[mt][2]), "=r"(aF[mt][3])
                    : "r"(addr));
            }
            // B fragments: 2 x ldmatrix.x4, each covers 2 n-tiles (16 n rows)
#pragma unroll
            for (int g = 0; g < 2; g++) {
                const int r  = wn * 32 + g * 16 + (lane & 7) + ((lane >> 4) << 3);
                const int ch = ks * 2 + ((lane >> 3) & 1);
                const int sw = ch ^ ((r >> 1) & 3);
                const uint32_t addr = bBase + r * 64 + sw * 16;
                asm volatile(
                    "ldmatrix.sync.aligned.m8n8.x4.shared.b16 {%0,%1,%2,%3}, [%4];\n"
                    : "=r"(bF[2 * g][0]), "=r"(bF[2 * g][1]),
                      "=r"(bF[2 * g + 1][0]), "=r"(bF[2 * g + 1][1])
                    : "r"(addr));
            }
#pragma unroll
            for (int mt = 0; mt < 4; mt++) {
#pragma unroll
                for (int nt = 0; nt < 4; nt++) {
                    asm volatile(
                        "mma.sync.aligned.m16n8k16.row.col.f32.bf16.bf16.f32 "
                        "{%0,%1,%2,%3}, {%4,%5,%6,%7}, {%8,%9}, {%0,%1,%2,%3};\n"
                        : "+f"(acc[mt][nt][0]), "+f"(acc[mt][nt][1]),
                          "+f"(acc[mt][nt][2]), "+f"(acc[mt][nt][3])
                        : "r"(aF[mt][0]), "r"(aF[mt][1]), "r"(aF[mt][2]), "r"(aF[mt][3]),
                          "r"(bF[nt][0]), "r"(bF[nt][1]));
                }
            }
        }
        __syncthreads();
    }

    // Epilogue: bias + activation, write fp32 gates to g_y
    const int segn = n0 >> 10;        // 0: tanh(z), 1/2: sigmoid(f/o)
    const int gq = lane >> 2;         // 0..7
    const int tq = lane & 3;          // 0..3
#pragma unroll
    for (int nt = 0; nt < 4; nt++) {
        const int col = n0 + wn * 32 + nt * 8 + tq * 2;
        const float b0 = bias[col];
        const float b1 = bias[col + 1];
#pragma unroll
        for (int mt = 0; mt < 4; mt++) {
            const int row = m0 + wm * 64 + mt * 16 + gq;
#pragma unroll
            for (int half = 0; half < 2; half++) {
                float v0 = acc[mt][nt][2 * half + 0] + b0;
                float v1 = acc[mt][nt][2 * half + 1] + b1;
                if (segn == 0) {
                    v0 = tanhf(v0);
                    v1 = tanhf(v1);
                } else {
                    v0 = 1.0f / (1.0f + __expf(-v0));
                    v1 = 1.0f / (1.0f + __expf(-v1));
                }
                float2 w = make_float2(v0, v1);
                *(float2*)&g_y[(size_t)(row + 8 * half) * NN + col] = w;
            }
        }
    }
}

// ---------------------------------------------------------------------------
// Scan pass 1: per (b, chunk, h) compute chunk composition
// ---------------------------------------------------------------------------
__global__ void __launch_bounds__(256) scan_pass1() {
    const int idx = blockIdx.x * 256 + threadIdx.x;
    const int h = idx & (HH - 1);
    const int rest = idx >> 10;
    const int ch = rest & (NCH - 1);
    const int b = rest >> 5;

    const float* base = g_y + (size_t)(b * SS + ch * CHLEN) * NN + h;

    float c = 0.0f, a = 1.0f;
#pragma unroll 8
    for (int t = 0; t < CHLEN; t++) {
        float z = base[(size_t)t * NN];
        float f = base[(size_t)t * NN + HH];
        c = fmaf(f, z - c, c);
        a *= (1.0f - f);
    }
    const int o = (ch * BB + b) * HH + h;
    g_Ac[o] = a;
    g_Bc[o] = c;
}

// ---------------------------------------------------------------------------
// Scan pass 2: per (b, h), sequential 32-step carry scan across chunks
// ---------------------------------------------------------------------------
__global__ void __launch_bounds__(256) scan_pass2() {
    const int idx = blockIdx.x * 256 + threadIdx.x;
    const int h = idx & (HH - 1);
    const int b = idx >> 10;

    float carry = 0.0f;
#pragma unroll
    for (int ch = 0; ch < NCH; ch++) {
        const int o = (ch * BB + b) * HH + h;
        g_C0[o] = carry;
        carry = fmaf(g_Ac[o], carry, g_Bc[o]);
    }
}

// ---------------------------------------------------------------------------
// Scan pass 3: re-run chunk scan with correct carry, write output + c_last
// ---------------------------------------------------------------------------
__global__ void __launch_bounds__(256) scan_pass3(float* __restrict__ out) {
    const int idx = blockIdx.x * 256 + threadIdx.x;
    const int h = idx & (HH - 1);
    const int rest = idx >> 10;
    const int ch = rest & (NCH - 1);
    const int b = rest >> 5;

    const float* base = g_y + (size_t)(b * SS + ch * CHLEN) * NN + h;
    float* orow = out + (size_t)(b * SS + ch * CHLEN) * HH + h;

    float c = g_C0[(ch * BB + b) * HH + h];
#pragma unroll 8
    for (int t = 0; t < CHLEN; t++) {
        float z = base[(size_t)t * NN];
        float f = base[(size_t)t * NN + HH];
        float o = base[(size_t)t * NN + 2 * HH];
        c = fmaf(f, z - c, c);
        orow[(size_t)t * HH] = o * c;
    }
    if (ch == NCH - 1) {
        out[(size_t)BB * SS * HH + b * HH + h] = c;
    }
}

// ---------------------------------------------------------------------------
extern "C" void kernel_launch(void* const* d_in, const int* in_sizes, int n_in,
                              void* d_out, int out_size) {
    const float* inp  = (const float*)d_in[0];   // [B, S, D]
    const float* W    = (const float*)d_in[1];   // [3H, D]
    const float* bias = (const float*)d_in[2];   // [3H]
    float* out = (float*)d_out;                  // [B,S,H] then [B,H]

    __nv_bfloat16 *ahi, *alo, *bhi, *blo;
    cudaGetSymbolAddress((void**)&ahi, g_Ahi);
    cudaGetSymbolAddress((void**)&alo, g_Alo);
    cudaGetSymbolAddress((void**)&bhi, g_Bhi);
    cudaGetSymbolAddress((void**)&blo, g_Blo);

    split_kernel<<<(MM * KK / 4 + 255) / 256, 256>>>(inp, ahi, alo, MM * KK / 4);
    split_kernel<<<(NN * KK / 4 + 255) / 256, 256>>>(W, bhi, blo, NN * KK / 4);

    dim3 ggrid(NN / 128, MM / 128);              // (24, 256)
    gemm_bf16x3<<<ggrid, 256>>>(bias);

    scan_pass1<<<(BB * HH * NCH) / 256, 256>>>();
    scan_pass2<<<(BB * HH) / 256, 256>>>();
    scan_pass3<<<(BB * HH * NCH) / 256, 256>>>(out);
}

// round 11
// speedup vs baseline: 4.8660x; 1.8064x over previous
#include <cuda_runtime.h>
#include <cuda.h>
#include <cuda_bf16.h>
#include <cstdint>

// Problem constants (QRNNLayer: B=16, S=2048, D=1024, H=1024)
#define BB 16
#define SS 2048
#define DD 1024
#define HH 1024
#define MM (BB * SS)        // 32768
#define NN (3 * HH)         // 3072
#define KK DD               // 1024
#define KEXT (3 * KK)       // 3072 extended K for bf16x3

// Scan config
#define NCH 32
#define CHLEN 64

// tcgen05 GEMM tiles
#define MT 256
#define NT 256
#define KT 64               // bf16 K per stage (128 B/row, SW128)
#define NST 3
#define NIT (KEXT / KT)     // 48
#define STAGE_A_BYTES (MT * 128)
#define STAGE_B_BYTES (NT * 128)
#define STAGE_BYTES (STAGE_A_BYTES + STAGE_B_BYTES)
#define SMEM_CTRL 1024
#define SMEM_NEED (SMEM_CTRL + NST * STAGE_BYTES + 1024)

// idesc kind::f16: dtype F32, a/b BF16, N=256, M=128
#define MMA_IDESC ((1u << 4) | (1u << 7) | (1u << 10) | ((NT / 8) << 17) | ((128 / 16) << 24))

// Arch-specific feature gate (tcgen05 exists only in arch-specific passes)
#if defined(__CUDA_ARCH_FEAT_SM103_ALL) || defined(__CUDA_ARCH_FEAT_SM100_ALL) || \
    defined(__CUDA_ARCH_SPECIFIC__) || defined(__CUDA_ARCH_FAMILY_SPECIFIC__)
#define HAS_TCGEN05 1
#else
#define HAS_TCGEN05 0
#endif

// Scratch (allocation-free: __device__ globals)
__device__ __nv_bfloat16 g_Aext[(size_t)MM * KEXT];   // [M][Ahi|Alo|Ahi]
__device__ __nv_bfloat16 g_Bext[(size_t)NN * KEXT];   // [N][Bhi|Bhi|Blo]
__device__ float g_y[(size_t)MM * NN];                // activated gates
__device__ float g_Ac[BB * HH * NCH];
__device__ float g_Bc[BB * HH * NCH];
__device__ float g_C0[BB * HH * NCH];

// ---------------------------------------------------------------------------
// Common helpers
// ---------------------------------------------------------------------------
__device__ __forceinline__ uint32_t smem_u32(const void* p) {
    return (uint32_t)__cvta_generic_to_shared(p);
}

#define MBAR_INIT(addr, cnt) \
    asm volatile("mbarrier.init.shared.b64 [%0], %1;" :: "r"(addr), "r"(cnt) : "memory")
#define MBAR_EXPECT_TX(addr, bytes) \
    asm volatile("mbarrier.arrive.expect_tx.shared.b64 _, [%0], %1;" :: "r"(addr), "r"(bytes) : "memory")
#define MBAR_WAIT(addr, parity) do {                                           \
    asm volatile(                                                              \
        "{\n\t.reg .pred P1;\n\t"                                              \
        "WAIT_LOOP_%=:\n\t"                                                    \
        "mbarrier.try_wait.parity.acquire.cta.shared::cta.b64 P1, [%0], %1, 0x989680;\n\t" \
        "@P1 bra.uni WAIT_DONE_%=;\n\t"                                        \
        "bra.uni WAIT_LOOP_%=;\n\t"                                            \
        "WAIT_DONE_%=:\n\t}"                                                   \
        :: "r"(addr), "r"(parity) : "memory");                                 \
} while (0)
#define TMA_LOAD_2D(dst, tm, cx, cy, mbar)                                     \
    asm volatile(                                                              \
        "cp.async.bulk.tensor.2d.shared::cta.global.tile.mbarrier::complete_tx::bytes " \
        "[%0], [%1, {%2, %3}], [%4];"                                          \
        :: "r"(dst), "l"(tm), "r"(cx), "r"(cy), "r"(mbar) : "memory")

// ---------------------------------------------------------------------------
// Split kernels: build extended-K bf16 operands
// ---------------------------------------------------------------------------
__device__ __forceinline__ void split4(float4 v, ushort4& ph, ushort4& pl) {
    __nv_bfloat16 h0 = __float2bfloat16(v.x), h1 = __float2bfloat16(v.y);
    __nv_bfloat16 h2 = __float2bfloat16(v.z), h3 = __float2bfloat16(v.w);
    __nv_bfloat16 l0 = __float2bfloat16(v.x - __bfloat162float(h0));
    __nv_bfloat16 l1 = __float2bfloat16(v.y - __bfloat162float(h1));
    __nv_bfloat16 l2 = __float2bfloat16(v.z - __bfloat162float(h2));
    __nv_bfloat16 l3 = __float2bfloat16(v.w - __bfloat162float(h3));
    ph.x = __bfloat16_as_ushort(h0); ph.y = __bfloat16_as_ushort(h1);
    ph.z = __bfloat16_as_ushort(h2); ph.w = __bfloat16_as_ushort(h3);
    pl.x = __bfloat16_as_ushort(l0); pl.y = __bfloat16_as_ushort(l1);
    pl.z = __bfloat16_as_ushort(l2); pl.w = __bfloat16_as_ushort(l3);
}

__global__ void __launch_bounds__(256) split_A(const float* __restrict__ src) {
    int i = blockIdx.x * 256 + threadIdx.x;
    int m = i >> 8;
    int k = (i & 255) * 4;
    ushort4 ph, pl;
    split4(((const float4*)src)[i], ph, pl);
    __nv_bfloat16* row = g_Aext + (size_t)m * KEXT;
    *(ushort4*)(row + k)          = ph;
    *(ushort4*)(row + KK + k)     = pl;
    *(ushort4*)(row + 2 * KK + k) = ph;
}

__global__ void __launch_bounds__(256) split_B(const float* __restrict__ src) {
    int i = blockIdx.x * 256 + threadIdx.x;
    int n = i >> 8;
    int k = (i & 255) * 4;
    ushort4 ph, pl;
    split4(((const float4*)src)[i], ph, pl);
    __nv_bfloat16* row = g_Bext + (size_t)n * KEXT;
    *(ushort4*)(row + k)          = ph;
    *(ushort4*)(row + KK + k)     = ph;
    *(ushort4*)(row + 2 * KK + k) = pl;
}

// ---------------------------------------------------------------------------
// tcgen05 helpers (only referenced in the arch-specific pass)
// ---------------------------------------------------------------------------
#if HAS_TCGEN05
#define TCG_ALLOC(sres, n) \
    asm volatile("tcgen05.alloc.cta_group::1.sync.aligned.shared::cta.b32 [%0], %1;" \
                 :: "r"(sres), "r"(n) : "memory")
#define TCG_DEALLOC(t, n) \
    asm volatile("tcgen05.dealloc.cta_group::1.sync.aligned.b32 %0, %1;" :: "r"(t), "r"(n))
#define TCG_RELINQ() \
    asm volatile("tcgen05.relinquish_alloc_permit.cta_group::1.sync.aligned;")
#define TCG_COMMIT(mbar) \
    asm volatile("tcgen05.commit.cta_group::1.mbarrier::arrive::one.shared::cluster.b64 [%0];" \
                 :: "r"(mbar) : "memory")
#define TCG_FENCE_AFTER()  asm volatile("tcgen05.fence::after_thread_sync;" ::: "memory")
#define TCG_WAIT_LD()      asm volatile("tcgen05.wait::ld.sync.aligned;" ::: "memory")

__device__ __forceinline__ void mma_f16_ss(uint32_t d, uint64_t ad, uint64_t bd,
                                           uint32_t idesc, bool en) {
    uint32_t e = en ? 1u : 0u;
    asm volatile(
        "{\n\t.reg .pred p;\n\t"
        "setp.ne.u32 p, %4, 0;\n\t"
        "tcgen05.mma.cta_group::1.kind::f16 [%0], %1, %2, %3, {%5, %5, %5, %5}, p;\n\t}"
        :: "r"(d), "l"(ad), "l"(bd), "r"(idesc), "r"(e), "r"(0u) : "memory");
}

__device__ __forceinline__ uint64_t make_desc(uint32_t saddr) {
    // SW128 K-major: layout=2, version=1, SBO=64, LBO=1
    return ((uint64_t)2 << 61) | ((uint64_t)1 << 46) | ((uint64_t)64 << 32) |
           ((uint64_t)1 << 16) | (uint64_t)((saddr >> 4) & 0x3FFF);
}

#define LDTM_X32(r, a)                                                         \
    asm volatile("tcgen05.ld.sync.aligned.32x32b.x32.b32 "                     \
        "{%0,%1,%2,%3,%4,%5,%6,%7,%8,%9,%10,%11,%12,%13,%14,%15,"              \
        "%16,%17,%18,%19,%20,%21,%22,%23,%24,%25,%26,%27,%28,%29,%30,%31}, [%32];" \
        : "=r"((r)[0]),"=r"((r)[1]),"=r"((r)[2]),"=r"((r)[3]),                 \
          "=r"((r)[4]),"=r"((r)[5]),"=r"((r)[6]),"=r"((r)[7]),                 \
          "=r"((r)[8]),"=r"((r)[9]),"=r"((r)[10]),"=r"((r)[11]),               \
          "=r"((r)[12]),"=r"((r)[13]),"=r"((r)[14]),"=r"((r)[15]),             \
          "=r"((r)[16]),"=r"((r)[17]),"=r"((r)[18]),"=r"((r)[19]),             \
          "=r"((r)[20]),"=r"((r)[21]),"=r"((r)[22]),"=r"((r)[23]),             \
          "=r"((r)[24]),"=r"((r)[25]),"=r"((r)[26]),"=r"((r)[27]),             \
          "=r"((r)[28]),"=r"((r)[29]),"=r"((r)[30]),"=r"((r)[31])              \
        : "r"(a))
#endif  // HAS_TCGEN05

// ---------------------------------------------------------------------------
// tcgen05 GEMM (arch-specific pass only). NOTE: __cluster_dims__(1,1,1) is
// required for tcgen05.commit's .shared::cluster mbarrier addressing.
// ---------------------------------------------------------------------------
__global__ void __launch_bounds__(128, 1) __cluster_dims__(1, 1, 1) gemm_tc(
    const __grid_constant__ CUtensorMap tmA,
    const __grid_constant__ CUtensorMap tmB,
    const float* __restrict__ bias)
{
#if HAS_TCGEN05
    extern __shared__ char smem_raw[];
    const uint32_t sb = (smem_u32(smem_raw) + 1023u) & ~1023u;
    const int tid = threadIdx.x;
    const int wid = tid >> 5, lid = tid & 31;
    const int m0 = blockIdx.y * MT;
    const int n0 = blockIdx.x * NT;

    if (wid == 0) TCG_ALLOC(sb, 512);
    __syncthreads();
    uint32_t tmem;
    asm volatile("ld.shared.b32 %0, [%1];" : "=r"(tmem) : "r"(sb));

    if (tid == 0) {
        for (int s = 0; s < NST; s++) { MBAR_INIT(sb + 64 + 8 * s, 1); MBAR_INIT(sb + 96 + 8 * s, 1); }
        MBAR_INIT(sb + 128, 1);
    }
    __syncthreads();

    if (tid == 0) {
        const uint32_t st0 = sb + SMEM_CTRL;
        #pragma unroll
        for (int it = 0; it < NST; it++) {
            const uint32_t sA = st0 + it * STAGE_BYTES;
            MBAR_EXPECT_TX(sb + 64 + 8 * it, STAGE_BYTES);
            TMA_LOAD_2D(sA, &tmA, it * KT, m0, sb + 64 + 8 * it);
            TMA_LOAD_2D(sA + STAGE_A_BYTES, &tmB, it * KT, n0, sb + 64 + 8 * it);
        }
        for (int it = 0; it < NIT; it++) {
            const int s = it % NST;
            MBAR_WAIT(sb + 64 + 8 * s, (it / NST) & 1);
            const uint32_t sA = st0 + s * STAGE_BYTES;
            const uint64_t ad = make_desc(sA);
            const uint64_t bd = make_desc(sA + STAGE_A_BYTES);
            #pragma unroll
            for (int ks = 0; ks < 4; ks++) {
                const bool en = (it > 0) || (ks > 0);
                mma_f16_ss(tmem,       ad + ks * 2,        bd + ks * 2, MMA_IDESC, en);
                mma_f16_ss(tmem + 256, ad + 1024 + ks * 2, bd + ks * 2, MMA_IDESC, en);
            }
            TCG_COMMIT(sb + 96 + 8 * s);
            const int prev = it - 1;
            const int nxt  = it + NST - 1;
            if (prev >= 0 && nxt < NIT) {
                const int sp = prev % NST;
                MBAR_WAIT(sb + 96 + 8 * sp, (prev / NST) & 1);
                const uint32_t pA = st0 + sp * STAGE_BYTES;
                MBAR_EXPECT_TX(sb + 64 + 8 * sp, STAGE_BYTES);
                TMA_LOAD_2D(pA, &tmA, nxt * KT, m0, sb + 64 + 8 * sp);
                TMA_LOAD_2D(pA + STAGE_A_BYTES, &tmB, nxt * KT, n0, sb + 64 + 8 * sp);
            }
        }
        TCG_COMMIT(sb + 128);
    }

    MBAR_WAIT(sb + 128, 0);
    TCG_FENCE_AFTER();

    const int seg = n0 >> 10;    // 0: tanh, 1/2: sigmoid
    #pragma unroll
    for (int h = 0; h < 2; h++) {
        const int row = m0 + h * 128 + wid * 32 + lid;
        float* yrow = g_y + (size_t)row * NN + n0;
        for (int cc = 0; cc < NT; cc += 32) {
            uint32_t r[32];
            LDTM_X32(r, tmem + h * 256 + cc);
            TCG_WAIT_LD();
            #pragma unroll
            for (int j4 = 0; j4 < 8; j4++) {
                const float4 bv = *(const float4*)(bias + n0 + cc + j4 * 4);
                float4 o;
                o.x = __uint_as_float(r[j4 * 4 + 0]) + bv.x;
                o.y = __uint_as_float(r[j4 * 4 + 1]) + bv.y;
                o.z = __uint_as_float(r[j4 * 4 + 2]) + bv.z;
                o.w = __uint_as_float(r[j4 * 4 + 3]) + bv.w;
                if (seg == 0) {
                    o.x = tanhf(o.x); o.y = tanhf(o.y); o.z = tanhf(o.z); o.w = tanhf(o.w);
                } else {
                    o.x = 1.0f / (1.0f + __expf(-o.x));
                    o.y = 1.0f / (1.0f + __expf(-o.y));
                    o.z = 1.0f / (1.0f + __expf(-o.z));
                    o.w = 1.0f / (1.0f + __expf(-o.w));
                }
                *(float4*)(yrow + cc + j4 * 4) = o;
            }
        }
    }

    __syncthreads();
    if (wid == 0) { TCG_RELINQ(); TCG_DEALLOC(tmem, 512); }
#endif  // HAS_TCGEN05
}

// ---------------------------------------------------------------------------
// Fallback mma.sync GEMM (non-arch-specific pass only)
// ---------------------------------------------------------------------------
#if !HAS_TCGEN05
__device__ __forceinline__ void cp16(uint32_t saddr, const void* g) {
    asm volatile("cp.async.cg.shared.global [%0], [%1], 16;\n" :: "r"(saddr), "l"(g));
}
#endif

#define FB_STAGE_BYTES 8192

__global__ void __launch_bounds__(256) gemm_fb(const float* __restrict__ bias)
{
#if !HAS_TCGEN05
    __shared__ __align__(128) __nv_bfloat16 sA[2][128 * 32];
    __shared__ __align__(128) __nv_bfloat16 sB[2][128 * 32];

    const int tid  = threadIdx.x;
    const int m0   = blockIdx.y * 128;
    const int n0   = blockIdx.x * 128;
    const int warp = tid >> 5;
    const int lane = tid & 31;
    const int wm   = warp >> 2;
    const int wn   = warp & 3;

    const uint32_t sAb = smem_u32(&sA[0][0]);
    const uint32_t sBb = smem_u32(&sB[0][0]);

    const int lrow0 = tid >> 2;
    const int lch   = tid & 3;

    float acc[4][4][4];
#pragma unroll
    for (int i = 0; i < 4; i++)
#pragma unroll
        for (int j = 0; j < 4; j++)
#pragma unroll
            for (int r = 0; r < 4; r++) acc[i][j][r] = 0.0f;

    auto load_stage = [&](int stage, int it) {
        const int kk = it * 32;
#pragma unroll
        for (int i = 0; i < 2; i++) {
            const int row = lrow0 + i * 64;
            const int sw  = lch ^ ((row >> 1) & 3);
            const uint32_t so = (uint32_t)(stage * FB_STAGE_BYTES + row * 64 + sw * 16);
            cp16(sAb + so, g_Aext + (size_t)(m0 + row) * KEXT + kk + lch * 8);
            cp16(sBb + so, g_Bext + (size_t)(n0 + row) * KEXT + kk + lch * 8);
        }
        asm volatile("cp.async.commit_group;\n" ::);
    };

    load_stage(0, 0);

    const int NITF = KEXT / 32;   // 96
    for (int it = 0; it < NITF; ++it) {
        if (it + 1 < NITF) {
            load_stage((it + 1) & 1, it + 1);
            asm volatile("cp.async.wait_group 1;\n" ::);
        } else {
            asm volatile("cp.async.wait_group 0;\n" ::);
        }
        __syncthreads();

        const int stage = it & 1;
        const uint32_t aBase = sAb + stage * FB_STAGE_BYTES;
        const uint32_t bBase = sBb + stage * FB_STAGE_BYTES;

#pragma unroll
        for (int ks = 0; ks < 2; ks++) {
            uint32_t aF[4][4];
            uint32_t bF[4][2];
#pragma unroll
            for (int mt = 0; mt < 4; mt++) {
                const int r  = wm * 64 + mt * 16 + (lane & 15);
                const int ch = ks * 2 + (lane >> 4);
                const int sw = ch ^ ((r >> 1) & 3);
                const uint32_t addr = aBase + r * 64 + sw * 16;
                asm volatile(
                    "ldmatrix.sync.aligned.m8n8.x4.shared.b16 {%0,%1,%2,%3}, [%4];\n"
                    : "=r"(aF[mt][0]), "=r"(aF[mt][1]), "=r"(aF[mt][2]), "=r"(aF[mt][3])
                    : "r"(addr));
            }
#pragma unroll
            for (int g = 0; g < 2; g++) {
                const int r  = wn * 32 + g * 16 + (lane & 7) + ((lane >> 4) << 3);
                const int ch = ks * 2 + ((lane >> 3) & 1);
                const int sw = ch ^ ((r >> 1) & 3);
                const uint32_t addr = bBase + r * 64 + sw * 16;
                asm volatile(
                    "ldmatrix.sync.aligned.m8n8.x4.shared.b16 {%0,%1,%2,%3}, [%4];\n"
                    : "=r"(bF[2 * g][0]), "=r"(bF[2 * g][1]),
                      "=r"(bF[2 * g + 1][0]), "=r"(bF[2 * g + 1][1])
                    : "r"(addr));
            }
#pragma unroll
            for (int mt = 0; mt < 4; mt++) {
#pragma unroll
                for (int nt = 0; nt < 4; nt++) {
                    asm volatile(
                        "mma.sync.aligned.m16n8k16.row.col.f32.bf16.bf16.f32 "
                        "{%0,%1,%2,%3}, {%4,%5,%6,%7}, {%8,%9}, {%0,%1,%2,%3};\n"
                        : "+f"(acc[mt][nt][0]), "+f"(acc[mt][nt][1]),
                          "+f"(acc[mt][nt][2]), "+f"(acc[mt][nt][3])
                        : "r"(aF[mt][0]), "r"(aF[mt][1]), "r"(aF[mt][2]), "r"(aF[mt][3]),
                          "r"(bF[nt][0]), "r"(bF[nt][1]));
                }
            }
        }
        __syncthreads();
    }

    const int segn = n0 >> 10;
    const int gq = lane >> 2;
    const int tq = lane & 3;
#pragma unroll
    for (int nt = 0; nt < 4; nt++) {
        const int col = n0 + wn * 32 + nt * 8 + tq * 2;
        const float b0 = bias[col];
        const float b1 = bias[col + 1];
#pragma unroll
        for (int mt = 0; mt < 4; mt++) {
            const int row = m0 + wm * 64 + mt * 16 + gq;
#pragma unroll
            for (int half = 0; half < 2; half++) {
                float v0 = acc[mt][nt][2 * half + 0] + b0;
                float v1 = acc[mt][nt][2 * half + 1] + b1;
                if (segn == 0) {
                    v0 = tanhf(v0);
                    v1 = tanhf(v1);
                } else {
                    v0 = 1.0f / (1.0f + __expf(-v0));
                    v1 = 1.0f / (1.0f + __expf(-v1));
                }
                float2 w = make_float2(v0, v1);
                *(float2*)&g_y[(size_t)(row + 8 * half) * NN + col] = w;
            }
        }
    }
#endif  // !HAS_TCGEN05
}

// ---------------------------------------------------------------------------
// Scan passes (unchanged, proven)
// ---------------------------------------------------------------------------
__global__ void __launch_bounds__(256) scan_pass1() {
    const int idx = blockIdx.x * 256 + threadIdx.x;
    const int h = idx & (HH - 1);
    const int rest = idx >> 10;
    const int ch = rest & (NCH - 1);
    const int b = rest >> 5;

    const float* base = g_y + (size_t)(b * SS + ch * CHLEN) * NN + h;

    float c = 0.0f, a = 1.0f;
#pragma unroll 8
    for (int t = 0; t < CHLEN; t++) {
        float z = base[(size_t)t * NN];
        float f = base[(size_t)t * NN + HH];
        c = fmaf(f, z - c, c);
        a *= (1.0f - f);
    }
    const int o = (ch * BB + b) * HH + h;
    g_Ac[o] = a;
    g_Bc[o] = c;
}

__global__ void __launch_bounds__(256) scan_pass2() {
    const int idx = blockIdx.x * 256 + threadIdx.x;
    const int h = idx & (HH - 1);
    const int b = idx >> 10;

    float carry = 0.0f;
#pragma unroll
    for (int ch = 0; ch < NCH; ch++) {
        const int o = (ch * BB + b) * HH + h;
        g_C0[o] = carry;
        carry = fmaf(g_Ac[o], carry, g_Bc[o]);
    }
}

__global__ void __launch_bounds__(256) scan_pass3(float* __restrict__ out) {
    const int idx = blockIdx.x * 256 + threadIdx.x;
    const int h = idx & (HH - 1);
    const int rest = idx >> 10;
    const int ch = rest & (NCH - 1);
    const int b = rest >> 5;

    const float* base = g_y + (size_t)(b * SS + ch * CHLEN) * NN + h;
    float* orow = out + (size_t)(b * SS + ch * CHLEN) * HH + h;

    float c = g_C0[(ch * BB + b) * HH + h];
#pragma unroll 8
    for (int t = 0; t < CHLEN; t++) {
        float z = base[(size_t)t * NN];
        float f = base[(size_t)t * NN + HH];
        float o = base[(size_t)t * NN + 2 * HH];
        c = fmaf(f, z - c, c);
        orow[(size_t)t * HH] = o * c;
    }
    if (ch == NCH - 1) {
        out[(size_t)BB * SS * HH + b * HH + h] = c;
    }
}

// ---------------------------------------------------------------------------
// Host side
// ---------------------------------------------------------------------------
typedef CUresult (CUDAAPI *EncodeFn)(
    CUtensorMap*, CUtensorMapDataType, cuuint32_t, void*,
    const cuuint64_t*, const cuuint64_t*, const cuuint32_t*, const cuuint32_t*,
    CUtensorMapInterleave, CUtensorMapSwizzle, CUtensorMapL2promotion,
    CUtensorMapFloatOOBfill);

static void build_tm(EncodeFn enc, CUtensorMap* tm, void* ptr,
                     uint64_t rows, uint32_t box_rows) {
    cuuint64_t dims[2]    = {(cuuint64_t)KEXT, (cuuint64_t)rows};
    cuuint64_t strides[1] = {(cuuint64_t)KEXT * 2};
    cuuint32_t box[2]     = {(cuuint32_t)KT, (cuuint32_t)box_rows};
    cuuint32_t es[2]      = {1, 1};
    enc(tm, CU_TENSOR_MAP_DATA_TYPE_BFLOAT16, 2, ptr, dims, strides, box, es,
        CU_TENSOR_MAP_INTERLEAVE_NONE, CU_TENSOR_MAP_SWIZZLE_128B,
        CU_TENSOR_MAP_L2_PROMOTION_L2_128B, CU_TENSOR_MAP_FLOAT_OOB_FILL_NONE);
}

extern "C" void kernel_launch(void* const* d_in, const int* in_sizes, int n_in,
                              void* d_out, int out_size) {
    const float* inp  = (const float*)d_in[0];   // [B, S, D]
    const float* W    = (const float*)d_in[1];   // [3H, D]
    const float* bias = (const float*)d_in[2];   // [3H]
    float* out = (float*)d_out;                  // [B,S,H] then [B,H]

    void* aext; void* bext;
    cudaGetSymbolAddress(&aext, g_Aext);
    cudaGetSymbolAddress(&bext, g_Bext);

    EncodeFn enc = nullptr;
    cudaDriverEntryPointQueryResult qst;
    cudaError_t est = cudaGetDriverEntryPoint("cuTensorMapEncodeTiled", (void**)&enc,
                                              cudaEnableDefault, &qst);

    CUtensorMap tmA = {}, tmB = {};
    if (est == cudaSuccess && enc != nullptr) {
        build_tm(enc, &tmA, aext, MM, MT);
        build_tm(enc, &tmB, bext, NN, NT);
    }

    cudaFuncSetAttribute(gemm_tc, cudaFuncAttributeMaxDynamicSharedMemorySize, SMEM_NEED);

    split_A<<<(MM * KK / 4) / 256, 256>>>(inp);
    split_B<<<(NN * KK / 4) / 256, 256>>>(W);

    // Both GEMMs launched; exactly one has a compiled body per target arch.
    dim3 tgrid(NN / NT, MM / MT);                // (12, 128)
    gemm_tc<<<tgrid, 128, SMEM_NEED>>>(tmA, tmB, bias);
    dim3 fgrid(NN / 128, MM / 128);              // (24, 256)
    gemm_fb<<<fgrid, 256>>>(bias);

    scan_pass1<<<(BB * HH * NCH) / 256, 256>>>();
    scan_pass2<<<(BB * HH) / 256, 256>>>();
    scan_pass3<<<(BB * HH * NCH) / 256, 256>>>(out);
}

// round 13
// speedup vs baseline: 5.0479x; 1.0374x over previous
#include <cuda_runtime.h>
#include <cuda.h>
#include <cuda_bf16.h>
#include <cstdint>

// Problem constants (QRNNLayer: B=16, S=2048, D=1024, H=1024)
#define BB 16
#define SS 2048
#define DD 1024
#define HH 1024
#define MM (BB * SS)        // 32768
#define NN (3 * HH)         // 3072
#define KK DD               // 1024
#define KK2 (2 * KK)        // stored operand width (hi|lo)
#define KEXT (3 * KK)       // virtual K for bf16x3

// Scan config
#define NCH 32
#define CHLEN 64

// tcgen05 GEMM tiles
#define MT 256
#define NT 256
#define KT 64               // bf16 K per stage (128 B/row, SW128)
#define NST 3
#define NIT (KEXT / KT)     // 48
#define STAGE_A_BYTES (MT * 128)
#define STAGE_B_BYTES (NT * 128)
#define STAGE_BYTES (STAGE_A_BYTES + STAGE_B_BYTES)
#define SMEM_CTRL 1024
#define SMEM_NEED (SMEM_CTRL + NST * STAGE_BYTES + 1024)

// idesc kind::f16: dtype F32, a/b BF16, N=256, M=128
#define MMA_IDESC ((1u << 4) | (1u << 7) | (1u << 10) | ((NT / 8) << 17) | ((128 / 16) << 24))

// Arch-specific feature gate (tcgen05 exists only in arch-specific passes)
#if defined(__CUDA_ARCH_FEAT_SM103_ALL) || defined(__CUDA_ARCH_FEAT_SM100_ALL) || \
    defined(__CUDA_ARCH_SPECIFIC__) || defined(__CUDA_ARCH_FAMILY_SPECIFIC__)
#define HAS_TCGEN05 1
#else
#define HAS_TCGEN05 0
#endif

// Scratch (allocation-free: __device__ globals)
__device__ __nv_bfloat16 g_A2[(size_t)MM * KK2];      // [M][Ahi|Alo]  128MB
__device__ __nv_bfloat16 g_B2[(size_t)NN * KK2];      // [N][Bhi|Blo]   12MB
__device__ float g_y[(size_t)MM * NN];                // activated gates
__device__ float g_Ac[BB * HH * NCH];
__device__ float g_Bc[BB * HH * NCH];
__device__ float g_C0[BB * HH * NCH];

// Virtual-K -> stored-coordinate maps (seg0:hi*hi, seg1:Alo*Bhi, seg2:Ahi*Blo)
#define A_CX(it) (((it) < 32 ? (it) : (it) - 32) * KT)
#define B_CX(it) (((it) < 16 ? (it) : (it) - 16) * KT)

// ---------------------------------------------------------------------------
// Common helpers
// ---------------------------------------------------------------------------
__device__ __forceinline__ uint32_t smem_u32(const void* p) {
    return (uint32_t)__cvta_generic_to_shared(p);
}

#define MBAR_INIT(addr, cnt) \
    asm volatile("mbarrier.init.shared.b64 [%0], %1;" :: "r"(addr), "r"(cnt) : "memory")
#define MBAR_EXPECT_TX(addr, bytes) \
    asm volatile("mbarrier.arrive.expect_tx.shared.b64 _, [%0], %1;" :: "r"(addr), "r"(bytes) : "memory")
#define MBAR_WAIT(addr, parity) do {                                           \
    asm volatile(                                                              \
        "{\n\t.reg .pred P1;\n\t"                                              \
        "WAIT_LOOP_%=:\n\t"                                                    \
        "mbarrier.try_wait.parity.acquire.cta.shared::cta.b64 P1, [%0], %1, 0x989680;\n\t" \
        "@P1 bra.uni WAIT_DONE_%=;\n\t"                                        \
        "bra.uni WAIT_LOOP_%=;\n\t"                                            \
        "WAIT_DONE_%=:\n\t}"                                                   \
        :: "r"(addr), "r"(parity) : "memory");                                 \
} while (0)
#define TMA_LOAD_2D(dst, tm, cx, cy, mbar)                                     \
    asm volatile(                                                              \
        "cp.async.bulk.tensor.2d.shared::cta.global.tile.mbarrier::complete_tx::bytes " \
        "[%0], [%1, {%2, %3}], [%4];"                                          \
        :: "r"(dst), "l"(tm), "r"(cx), "r"(cy), "r"(mbar) : "memory")

// ---------------------------------------------------------------------------
// Split kernel: float row [len KK] -> bf16 row [Xhi(KK) | Xlo(KK)]
// ---------------------------------------------------------------------------
__global__ void __launch_bounds__(256) split_hl(const float* __restrict__ src,
                                               __nv_bfloat16* __restrict__ dst) {
    int i = blockIdx.x * 256 + threadIdx.x;    // over rows*KK/4
    int r = i >> 8;                            // KK/4 = 256 float4 per row
    int k = (i & 255) * 4;
    float4 v = ((const float4*)src)[i];
    __nv_bfloat16 h0 = __float2bfloat16(v.x), h1 = __float2bfloat16(v.y);
    __nv_bfloat16 h2 = __float2bfloat16(v.z), h3 = __float2bfloat16(v.w);
    __nv_bfloat16 l0 = __float2bfloat16(v.x - __bfloat162float(h0));
    __nv_bfloat16 l1 = __float2bfloat16(v.y - __bfloat162float(h1));
    __nv_bfloat16 l2 = __float2bfloat16(v.z - __bfloat162float(h2));
    __nv_bfloat16 l3 = __float2bfloat16(v.w - __bfloat162float(h3));
    ushort4 ph, pl;
    ph.x = __bfloat16_as_ushort(h0); ph.y = __bfloat16_as_ushort(h1);
    ph.z = __bfloat16_as_ushort(h2); ph.w = __bfloat16_as_ushort(h3);
    pl.x = __bfloat16_as_ushort(l0); pl.y = __bfloat16_as_ushort(l1);
    pl.z = __bfloat16_as_ushort(l2); pl.w = __bfloat16_as_ushort(l3);
    __nv_bfloat16* row = dst + (size_t)r * KK2;
    *(ushort4*)(row + k)      = ph;
    *(ushort4*)(row + KK + k) = pl;
}

// ---------------------------------------------------------------------------
// tcgen05 helpers (only referenced in the arch-specific pass)
// ---------------------------------------------------------------------------
#if HAS_TCGEN05
#define TCG_ALLOC(sres, n) \
    asm volatile("tcgen05.alloc.cta_group::1.sync.aligned.shared::cta.b32 [%0], %1;" \
                 :: "r"(sres), "r"(n) : "memory")
#define TCG_DEALLOC(t, n) \
    asm volatile("tcgen05.dealloc.cta_group::1.sync.aligned.b32 %0, %1;" :: "r"(t), "r"(n))
#define TCG_RELINQ() \
    asm volatile("tcgen05.relinquish_alloc_permit.cta_group::1.sync.aligned;")
#define TCG_COMMIT(mbar) \
    asm volatile("tcgen05.commit.cta_group::1.mbarrier::arrive::one.shared::cluster.b64 [%0];" \
                 :: "r"(mbar) : "memory")
#define TCG_FENCE_AFTER()  asm volatile("tcgen05.fence::after_thread_sync;" ::: "memory")
#define TCG_WAIT_LD()      asm volatile("tcgen05.wait::ld.sync.aligned;" ::: "memory")

__device__ __forceinline__ void mma_f16_ss(uint32_t d, uint64_t ad, uint64_t bd,
                                           uint32_t idesc, bool en) {
    uint32_t e = en ? 1u : 0u;
    asm volatile(
        "{\n\t.reg .pred p;\n\t"
        "setp.ne.u32 p, %4, 0;\n\t"
        "tcgen05.mma.cta_group::1.kind::f16 [%0], %1, %2, %3, {%5, %5, %5, %5}, p;\n\t}"
        :: "r"(d), "l"(ad), "l"(bd), "r"(idesc), "r"(e), "r"(0u) : "memory");
}

__device__ __forceinline__ uint64_t make_desc(uint32_t saddr) {
    // SW128 K-major: layout=2, version=1, SBO=64, LBO=1
    return ((uint64_t)2 << 61) | ((uint64_t)1 << 46) | ((uint64_t)64 << 32) |
           ((uint64_t)1 << 16) | (uint64_t)((saddr >> 4) & 0x3FFF);
}

#define LDTM_X32(r, a)                                                         \
    asm volatile("tcgen05.ld.sync.aligned.32x32b.x32.b32 "                     \
        "{%0,%1,%2,%3,%4,%5,%6,%7,%8,%9,%10,%11,%12,%13,%14,%15,"              \
        "%16,%17,%18,%19,%20,%21,%22,%23,%24,%25,%26,%27,%28,%29,%30,%31}, [%32];" \
        : "=r"((r)[0]),"=r"((r)[1]),"=r"((r)[2]),"=r"((r)[3]),                 \
          "=r"((r)[4]),"=r"((r)[5]),"=r"((r)[6]),"=r"((r)[7]),                 \
          "=r"((r)[8]),"=r"((r)[9]),"=r"((r)[10]),"=r"((r)[11]),               \
          "=r"((r)[12]),"=r"((r)[13]),"=r"((r)[14]),"=r"((r)[15]),             \
          "=r"((r)[16]),"=r"((r)[17]),"=r"((r)[18]),"=r"((r)[19]),             \
          "=r"((r)[20]),"=r"((r)[21]),"=r"((r)[22]),"=r"((r)[23]),             \
          "=r"((r)[24]),"=r"((r)[25]),"=r"((r)[26]),"=r"((r)[27]),             \
          "=r"((r)[28]),"=r"((r)[29]),"=r"((r)[30]),"=r"((r)[31])              \
        : "r"(a))
#endif  // HAS_TCGEN05

// ---------------------------------------------------------------------------
// tcgen05 GEMM (arch-specific pass only), warp-specialized:
//   tid 0  = producer: waits done-ring, expect_tx, TMA A+B
//   tid 32 = consumer: waits full, issues 8 MMAs, commit -> done
// ---------------------------------------------------------------------------
__global__ void __launch_bounds__(128, 1) __cluster_dims__(1, 1, 1) gemm_tc(
    const __grid_constant__ CUtensorMap tmA,
    const __grid_constant__ CUtensorMap tmB,
    const float* __restrict__ bias)
{
#if HAS_TCGEN05
    extern __shared__ char smem_raw[];
    const uint32_t sb = (smem_u32(smem_raw) + 1023u) & ~1023u;
    const int tid = threadIdx.x;
    const int wid = tid >> 5, lid = tid & 31;
    const int m0 = blockIdx.y * MT;
    const int n0 = blockIdx.x * NT;

    if (wid == 0) TCG_ALLOC(sb, 512);
    __syncthreads();
    uint32_t tmem;
    asm volatile("ld.shared.b32 %0, [%1];" : "=r"(tmem) : "r"(sb));

    if (tid == 0) {
        for (int s = 0; s < NST; s++) { MBAR_INIT(sb + 64 + 8 * s, 1); MBAR_INIT(sb + 96 + 8 * s, 1); }
        MBAR_INIT(sb + 128, 1);
    }
    __syncthreads();

    const uint32_t st0 = sb + SMEM_CTRL;

    if (tid == 0) {
        // Producer: run ahead, bounded by the NST-deep done-ring.
        for (int it = 0; it < NIT; it++) {
            const int s = it % NST;
            if (it >= NST) MBAR_WAIT(sb + 96 + 8 * s, ((it - NST) / NST) & 1);
            const uint32_t sA = st0 + s * STAGE_BYTES;
            MBAR_EXPECT_TX(sb + 64 + 8 * s, STAGE_BYTES);
            TMA_LOAD_2D(sA, &tmA, A_CX(it), m0, sb + 64 + 8 * s);
            TMA_LOAD_2D(sA + STAGE_A_BYTES, &tmB, B_CX(it), n0, sb + 64 + 8 * s);
        }
    } else if (tid == 32) {
        // Consumer: wait full, 8 MMA dispatches, commit to done-ring.
        for (int it = 0; it < NIT; it++) {
            const int s = it % NST;
            MBAR_WAIT(sb + 64 + 8 * s, (it / NST) & 1);
            const uint32_t sA = st0 + s * STAGE_BYTES;
            const uint64_t ad = make_desc(sA);
            const uint64_t bd = make_desc(sA + STAGE_A_BYTES);
            #pragma unroll
            for (int ks = 0; ks < 4; ks++) {
                const bool en = (it > 0) || (ks > 0);
                mma_f16_ss(tmem,       ad + ks * 2,        bd + ks * 2, MMA_IDESC, en);
                mma_f16_ss(tmem + 256, ad + 1024 + ks * 2, bd + ks * 2, MMA_IDESC, en);
            }
            TCG_COMMIT(sb + 96 + 8 * s);
        }
        TCG_COMMIT(sb + 128);
    }

    MBAR_WAIT(sb + 128, 0);
    TCG_FENCE_AFTER();

    // Epilogue: bias + activation -> g_y
    const int seg = n0 >> 10;    // 0: tanh, 1/2: sigmoid
    #pragma unroll
    for (int h = 0; h < 2; h++) {
        const int row = m0 + h * 128 + wid * 32 + lid;
        float* yrow = g_y + (size_t)row * NN + n0;
        for (int cc = 0; cc < NT; cc += 32) {
            uint32_t r[32];
            LDTM_X32(r, tmem + h * 256 + cc);
            TCG_WAIT_LD();
            #pragma unroll
            for (int j4 = 0; j4 < 8; j4++) {
                const float4 bv = *(const float4*)(bias + n0 + cc + j4 * 4);
                float4 o;
                o.x = __uint_as_float(r[j4 * 4 + 0]) + bv.x;
                o.y = __uint_as_float(r[j4 * 4 + 1]) + bv.y;
                o.z = __uint_as_float(r[j4 * 4 + 2]) + bv.z;
                o.w = __uint_as_float(r[j4 * 4 + 3]) + bv.w;
                if (seg == 0) {
                    o.x = tanhf(o.x); o.y = tanhf(o.y); o.z = tanhf(o.z); o.w = tanhf(o.w);
                } else {
                    o.x = 1.0f / (1.0f + __expf(-o.x));
                    o.y = 1.0f / (1.0f + __expf(-o.y));
                    o.z = 1.0f / (1.0f + __expf(-o.z));
                    o.w = 1.0f / (1.0f + __expf(-o.w));
                }
                *(float4*)(yrow + cc + j4 * 4) = o;
            }
        }
    }

    __syncthreads();
    if (wid == 0) { TCG_RELINQ(); TCG_DEALLOC(tmem, 512); }
#endif  // HAS_TCGEN05
}

// ---------------------------------------------------------------------------
// Fallback mma.sync GEMM (non-arch-specific pass only), virtual K=3072 over
// the 2-segment stored layout.
// ---------------------------------------------------------------------------
#if !HAS_TCGEN05
__device__ __forceinline__ void cp16(uint32_t saddr, const void* g) {
    asm volatile("cp.async.cg.shared.global [%0], [%1], 16;\n" :: "r"(saddr), "l"(g));
}
#endif

#define FB_STAGE_BYTES 8192

__global__ void __launch_bounds__(256) gemm_fb(const float* __restrict__ bias)
{
#if !HAS_TCGEN05
    __shared__ __align__(128) __nv_bfloat16 sA[2][128 * 32];
    __shared__ __align__(128) __nv_bfloat16 sB[2][128 * 32];

    const int tid  = threadIdx.x;
    const int m0   = blockIdx.y * 128;
    const int n0   = blockIdx.x * 128;
    const int warp = tid >> 5;
    const int lane = tid & 31;
    const int wm   = warp >> 2;
    const int wn   = warp & 3;

    const uint32_t sAb = smem_u32(&sA[0][0]);
    const uint32_t sBb = smem_u32(&sB[0][0]);

    const int lrow0 = tid >> 2;
    const int lch   = tid & 3;

    float acc[4][4][4];
#pragma unroll
    for (int i = 0; i < 4; i++)
#pragma unroll
        for (int j = 0; j < 4; j++)
#pragma unroll
            for (int r = 0; r < 4; r++) acc[i][j][r] = 0.0f;

    auto load_stage = [&](int stage, int it) {
        const int kk = it * 32;                       // virtual k
        const int akk = (kk < 2048) ? kk : kk - 2048; // [Ahi|Alo], seg2 -> Ahi
        const int bkk = (kk < 1024) ? kk : kk - 1024; // [Bhi|Blo], seg1 -> Bhi
#pragma unroll
        for (int i = 0; i < 2; i++) {
            const int row = lrow0 + i * 64;
            const int sw  = lch ^ ((row >> 1) & 3);
            const uint32_t so = (uint32_t)(stage * FB_STAGE_BYTES + row * 64 + sw * 16);
            cp16(sAb + so, g_A2 + (size_t)(m0 + row) * KK2 + akk + lch * 8);
            cp16(sBb + so, g_B2 + (size_t)(n0 + row) * KK2 + bkk + lch * 8);
        }
        asm volatile("cp.async.commit_group;\n" ::);
    };

    load_stage(0, 0);

    const int NITF = KEXT / 32;   // 96
    for (int it = 0; it < NITF; ++it) {
        if (it + 1 < NITF) {
            load_stage((it + 1) & 1, it + 1);
            asm volatile("cp.async.wait_group 1;\n" ::);
        } else {
            asm volatile("cp.async.wait_group 0;\n" ::);
        }
        __syncthreads();

        const int stage = it & 1;
        const uint32_t aBase = sAb + stage * FB_STAGE_BYTES;
        const uint32_t bBase = sBb + stage * FB_STAGE_BYTES;

#pragma unroll
        for (int ks = 0; ks < 2; ks++) {
            uint32_t aF[4][4];
            uint32_t bF[4][2];
#pragma unroll
            for (int mt = 0; mt < 4; mt++) {
                const int r  = wm * 64 + mt * 16 + (lane & 15);
                const int ch = ks * 2 + (lane >> 4);
                const int sw = ch ^ ((r >> 1) & 3);
                const uint32_t addr = aBase + r * 64 + sw * 16;
                asm volatile(
                    "ldmatrix.sync.aligned.m8n8.x4.shared.b16 {%0,%1,%2,%3}, [%4];\n"
                    : "=r"(aF[mt][0]), "=r"(aF[mt][1]), "=r"(aF[mt][2]), "=r"(aF[mt][3])
                    : "r"(addr));
            }
#pragma unroll
            for (int g = 0; g < 2; g++) {
                const int r  = wn * 32 + g * 16 + (lane & 7) + ((lane >> 4) << 3);
                const int ch = ks * 2 + ((lane >> 3) & 1);
                const int sw = ch ^ ((r >> 1) & 3);
                const uint32_t addr = bBase + r * 64 + sw * 16;
                asm volatile(
                    "ldmatrix.sync.aligned.m8n8.x4.shared.b16 {%0,%1,%2,%3}, [%4];\n"
                    : "=r"(bF[2 * g][0]), "=r"(bF[2 * g][1]),
                      "=r"(bF[2 * g + 1][0]), "=r"(bF[2 * g + 1][1])
                    : "r"(addr));
            }
#pragma unroll
            for (int mt = 0; mt < 4; mt++) {
#pragma unroll
                for (int nt = 0; nt < 4; nt++) {
                    asm volatile(
                        "mma.sync.aligned.m16n8k16.row.col.f32.bf16.bf16.f32 "
                        "{%0,%1,%2,%3}, {%4,%5,%6,%7}, {%8,%9}, {%0,%1,%2,%3};\n"
                        : "+f"(acc[mt][nt][0]), "+f"(acc[mt][nt][1]),
                          "+f"(acc[mt][nt][2]), "+f"(acc[mt][nt][3])
                        : "r"(aF[mt][0]), "r"(aF[mt][1]), "r"(aF[mt][2]), "r"(aF[mt][3]),
                          "r"(bF[nt][0]), "r"(bF[nt][1]));
                }
            }
        }
        __syncthreads();
    }

    const int segn = n0 >> 10;
    const int gq = lane >> 2;
    const int tq = lane & 3;
#pragma unroll
    for (int nt = 0; nt < 4; nt++) {
        const int col = n0 + wn * 32 + nt * 8 + tq * 2;
        const float b0 = bias[col];
        const float b1 = bias[col + 1];
#pragma unroll
        for (int mt = 0; mt < 4; mt++) {
            const int row = m0 + wm * 64 + mt * 16 + gq;
#pragma unroll
            for (int half = 0; half < 2; half++) {
                float v0 = acc[mt][nt][2 * half + 0] + b0;
                float v1 = acc[mt][nt][2 * half + 1] + b1;
                if (segn == 0) {
                    v0 = tanhf(v0);
                    v1 = tanhf(v1);
                } else {
                    v0 = 1.0f / (1.0f + __expf(-v0));
                    v1 = 1.0f / (1.0f + __expf(-v1));
                }
                float2 w = make_float2(v0, v1);
                *(float2*)&g_y[(size_t)(row + 8 * half) * NN + col] = w;
            }
        }
    }
#endif  // !HAS_TCGEN05
}

// ---------------------------------------------------------------------------
// Scan passes (unchanged, proven)
// ---------------------------------------------------------------------------
__global__ void __launch_bounds__(256) scan_pass1() {
    const int idx = blockIdx.x * 256 + threadIdx.x;
    const int h = idx & (HH - 1);
    const int rest = idx >> 10;
    const int ch = rest & (NCH - 1);
    const int b = rest >> 5;

    const float* base = g_y + (size_t)(b * SS + ch * CHLEN) * NN + h;

    float c = 0.0f, a = 1.0f;
#pragma unroll 8
    for (int t = 0; t < CHLEN; t++) {
        float z = base[(size_t)t * NN];
        float f = base[(size_t)t * NN + HH];
        c = fmaf(f, z - c, c);
        a *= (1.0f - f);
    }
    const int o = (ch * BB + b) * HH + h;
    g_Ac[o] = a;
    g_Bc[o] = c;
}

__global__ void __launch_bounds__(256) scan_pass2() {
    const int idx = blockIdx.x * 256 + threadIdx.x;
    const int h = idx & (HH - 1);
    const int b = idx >> 10;

    float carry = 0.0f;
#pragma unroll
    for (int ch = 0; ch < NCH; ch++) {
        const int o = (ch * BB + b) * HH + h;
        g_C0[o] = carry;
        carry = fmaf(g_Ac[o], carry, g_Bc[o]);
    }
}

__global__ void __launch_bounds__(256) scan_pass3(float* __restrict__ out) {
    const int idx = blockIdx.x * 256 + threadIdx.x;
    const int h = idx & (HH - 1);
    const int rest = idx >> 10;
    const int ch = rest & (NCH - 1);
    const int b = rest >> 5;

    const float* base = g_y + (size_t)(b * SS + ch * CHLEN) * NN + h;
    float* orow = out + (size_t)(b * SS + ch * CHLEN) * HH + h;

    float c = g_C0[(ch * BB + b) * HH + h];
#pragma unroll 8
    for (int t = 0; t < CHLEN; t++) {
        float z = base[(size_t)t * NN];
        float f = base[(size_t)t * NN + HH];
        float o = base[(size_t)t * NN + 2 * HH];
        c = fmaf(f, z - c, c);
        orow[(size_t)t * HH] = o * c;
    }
    if (ch == NCH - 1) {
        out[(size_t)BB * SS * HH + b * HH + h] = c;
    }
}

// ---------------------------------------------------------------------------
// Host side
// ---------------------------------------------------------------------------
typedef CUresult (CUDAAPI *EncodeFn)(
    CUtensorMap*, CUtensorMapDataType, cuuint32_t, void*,
    const cuuint64_t*, const cuuint64_t*, const cuuint32_t*, const cuuint32_t*,
    CUtensorMapInterleave, CUtensorMapSwizzle, CUtensorMapL2promotion,
    CUtensorMapFloatOOBfill);

static void build_tm(EncodeFn enc, CUtensorMap* tm, void* ptr,
                     uint64_t rows, uint32_t box_rows) {
    cuuint64_t dims[2]    = {(cuuint64_t)KK2, (cuuint64_t)rows};
    cuuint64_t strides[1] = {(cuuint64_t)KK2 * 2};
    cuuint32_t box[2]     = {(cuuint32_t)KT, (cuuint32_t)box_rows};
    cuuint32_t es[2]      = {1, 1};
    enc(tm, CU_TENSOR_MAP_DATA_TYPE_BFLOAT16, 2, ptr, dims, strides, box, es,
        CU_TENSOR_MAP_INTERLEAVE_NONE, CU_TENSOR_MAP_SWIZZLE_128B,
        CU_TENSOR_MAP_L2_PROMOTION_L2_128B, CU_TENSOR_MAP_FLOAT_OOB_FILL_NONE);
}

extern "C" void kernel_launch(void* const* d_in, const int* in_sizes, int n_in,
                              void* d_out, int out_size) {
    const float* inp  = (const float*)d_in[0];   // [B, S, D]
    const float* W    = (const float*)d_in[1];   // [3H, D]
    const float* bias = (const float*)d_in[2];   // [3H]
    float* out = (float*)d_out;                  // [B,S,H] then [B,H]

    void* a2; void* b2;
    cudaGetSymbolAddress(&a2, g_A2);
    cudaGetSymbolAddress(&b2, g_B2);

    EncodeFn enc = nullptr;
    cudaDriverEntryPointQueryResult qst;
    cudaError_t est = cudaGetDriverEntryPoint("cuTensorMapEncodeTiled", (void**)&enc,
                                              cudaEnableDefault, &qst);

    CUtensorMap tmA = {}, tmB = {};
    if (est == cudaSuccess && enc != nullptr) {
        build_tm(enc, &tmA, a2, MM, MT);
        build_tm(enc, &tmB, b2, NN, NT);
    }

    cudaFuncSetAttribute(gemm_tc, cudaFuncAttributeMaxDynamicSharedMemorySize, SMEM_NEED);

    split_hl<<<(MM * KK / 4) / 256, 256>>>(inp, (__nv_bfloat16*)a2);
    split_hl<<<(NN * KK / 4) / 256, 256>>>(W,   (__nv_bfloat16*)b2);

    // Both GEMMs launched; exactly one has a compiled body per target arch.
    dim3 tgrid(NN / NT, MM / MT);                // (12, 128)
    gemm_tc<<<tgrid, 128, SMEM_NEED>>>(tmA, tmB, bias);
    dim3 fgrid(NN / 128, MM / 128);              // (24, 256)
    gemm_fb<<<fgrid, 256>>>(bias);

    scan_pass1<<<(BB * HH * NCH) / 256, 256>>>();
    scan_pass2<<<(BB * HH) / 256, 256>>>();
    scan_pass3<<<(BB * HH * NCH) / 256, 256>>>(out);
}